// round 11
// baseline (speedup 1.0000x reference)
#include <cuda_runtime.h>
#include <cuda_fp16.h>
#include <cstdint>

// Shapes (fixed by the problem)
#define CH    32
#define DD    36
#define HH    48
#define WW    48
#define HW    (HH*WW)          // 2304
#define DHW   (DD*HW)          // 82944
#define PP    9
#define P2    81
#define ND    (DD/PP)          // 4
#define NW    (HW/PP)          // 256
#define LL    (ND*NW)          // 1024
#define M2    162              // 2*P2
#define KE    192              // row: [hi,lo] interleaved pairs j=0..80 (+pad 162..191)
#define VSCALE 1024.0f         // pre-scale so lo stays in fp16 normal range

// ---------------- device scratch (no allocs allowed) ----------------
__device__ uint32_t g_weff2[96 * 96];         // Weff2[n][j]: packed (hi,lo) per j
__device__ __half g_u2x[CH * LL * KE];        // conv(x) rows, [hi,lo] interleaved
__device__ __half g_u2y[CH * LL * KE];
__device__ __half g_pA[CH * LL * KE];         // px rows, [hi,lo] interleaved
__device__ __half g_pB[CH * LL * KE];

// ---------------- helpers ----------------
__device__ __forceinline__ uint32_t smem_u32(const void* p) {
    uint32_t a;
    asm("{ .reg .u64 t; cvta.to.shared.u64 t, %1; cvt.u32.u64 %0, t; }"
        : "=r"(a) : "l"(p));
    return a;
}
__device__ __forceinline__ void cpa16(uint32_t s, const void* g) {
    asm volatile("cp.async.cg.shared.global [%0], [%1], 16;" :: "r"(s), "l"(g));
}
__device__ __forceinline__ void ldmx4(uint32_t& r0, uint32_t& r1,
                                      uint32_t& r2, uint32_t& r3, uint32_t a) {
    asm volatile("ldmatrix.sync.aligned.m8n8.x4.shared.b16 {%0,%1,%2,%3}, [%4];"
                 : "=r"(r0), "=r"(r1), "=r"(r2), "=r"(r3) : "r"(a));
}
__device__ __forceinline__ void mma16816(float* d, const uint32_t* a,
                                         uint32_t b0, uint32_t b1) {
    asm volatile(
        "mma.sync.aligned.m16n8k16.row.col.f32.f16.f16.f32 "
        "{%0,%1,%2,%3}, {%4,%5,%6,%7}, {%8,%9}, {%0,%1,%2,%3};"
        : "+f"(d[0]), "+f"(d[1]), "+f"(d[2]), "+f"(d[3])
        : "r"(a[0]), "r"(a[1]), "r"(a[2]), "r"(a[3]), "r"(b0), "r"(b1));
}
// pack value v (already final-scaled) into (hi, lo) fp16 pair as uint32
__device__ __forceinline__ uint32_t pack_hilo(float s) {
    __half hb = __float2half_rn(s);
    __half lb = __float2half_rn(s - __half2float(hb));
    return (uint32_t)__half_as_ushort(hb) |
           ((uint32_t)__half_as_ushort(lb) << 16);
}

// ---------------- Kernel 0: Weff2 = split((W2 @ W1)^T * VSCALE) ------------
// Row n (output k index), uint j holds (hi,lo) of Weff[n][j]*VSCALE. Pads zero.
__global__ void weff_kernel(const float* __restrict__ W1,
                            const float* __restrict__ W2,
                            uint32_t* __restrict__ We2) {
    __shared__ float w2row[M2];
    int k = blockIdx.x;     // 0..95
    int j = threadIdx.x;    // 0..95
    if (k < P2)
        for (int m = j; m < M2; m += 96) w2row[m] = W2[k * M2 + m];
    __syncthreads();
    float s = 0.f;
    if (k < P2 && j < P2) {
        #pragma unroll 6
        for (int m = 0; m < M2; m++) s += w2row[m] * W1[m * P2 + j];
        s *= VSCALE;
    }
    We2[k * 96 + j] = pack_hilo(s);
}

// ---------------- Kernel 1: conv + unfold -> fp16 hi/lo rows ---------------
// Block: one d-slice (pd,kd) x 32 pw. Coalesced reads, conv in smem, then
// write 9 packed uints per (c,l) row at uint index j = kd*9+kw.
#define CV_THREADS 288
#define CV_SMEM ((9216 + 9216 + 1024 + 32) * 4)    // 73984 B
__global__ __launch_bounds__(CV_THREADS)
void conv_unfold(const float* __restrict__ x, const float* __restrict__ y,
                 const float* __restrict__ Wi, const float* __restrict__ bi,
                 const float* __restrict__ Wf, const float* __restrict__ bf_,
                 __half* __restrict__ ux, __half* __restrict__ uy) {
    extern __shared__ float cs[];
    float* xs = cs;            // [32][288]
    float* us = cs + 9216;     // [32][288]
    float* ws = cs + 18432;    // [32][32]
    float* bs = cs + 19456;    // [32]

    int z = blockIdx.z;
    const float* src = z ? y : x;
    const float* Wc  = z ? Wf : Wi;
    const float* bc  = z ? bf_ : bi;
    __half* U        = z ? uy : ux;

    int tid = threadIdx.x;
    int d   = blockIdx.x;              // 0..35
    int pwb = blockIdx.y;              // 0..7
    int pd = d / PP, kd = d - pd * PP;

    for (int i = tid; i < CH * CH; i += CV_THREADS) ws[i] = Wc[i];
    if (tid < CH) bs[tid] = bc[tid];

    {   // coalesced load: 32 ch x 288 floats
        const float4* x4 = (const float4*)src;
        float4* xs4 = (float4*)xs;
        int base = d * (HW / 4) + pwb * 72;
        #pragma unroll
        for (int it = 0; it < 8; it++) {
            int idx = it * CV_THREADS + tid;
            int i = idx / 72, q = idx - i * 72;
            xs4[idx] = x4[i * (DHW / 4) + base + q];
        }
    }
    __syncthreads();

    {   // conv: each thread owns one voxel
        int v = tid;
        float xv[CH];
        #pragma unroll
        for (int i = 0; i < CH; i++) xv[i] = xs[i * 288 + v];
        #pragma unroll 4
        for (int c = 0; c < CH; c++) {
            float s = bs[c];
            #pragma unroll
            for (int i = 0; i < CH; i++) s += ws[c * CH + i] * xv[i];
            us[c * 288 + v] = s;
        }
    }
    __syncthreads();

    {   // write packed (hi,lo) uints; row (c,l): 9 uints at j = kd*9+kw
        int l0 = pd * NW + pwb * 32;
        for (int r = tid; r < 1024; r += CV_THREADS) {
            int c = r >> 5, pw = r & 31;
            uint32_t* p = (uint32_t*)U + ((size_t)(c * LL + l0 + pw)) * 96;
            #pragma unroll
            for (int kw = 0; kw < PP; kw++) {
                float s = us[c * 288 + pw * PP + kw] * VSCALE;
                p[kd * PP + kw] = pack_hilo(s);
            }
            if (kd == 0) {
                #pragma unroll
                for (int q = P2; q < 96; q++) p[q] = 0u;
            }
        }
    }
}

// ---------------- Kernel 2: res_trans on tensor cores ----------------------
// per (l-block 128, c, z): A = U2 rows [128][192]h, B = Weff2 [96][192]h.
// acc -> *2^-20 -> leaky -> *1024 -> split -> staged -> coalesced out.
#define RT2_SMEM (49152 + 36864)          // A + B = 86016 B (stage reuses A)
__global__ __launch_bounds__(256, 2)
void res_trans_tc(const __half* __restrict__ U2x, const __half* __restrict__ U2y,
                  __half* __restrict__ P0, __half* __restrict__ P1) {
    extern __shared__ char smb[];
    uint32_t sA = smem_u32(smb);
    uint32_t sB = sA + 49152;

    int z  = blockIdx.z;
    const __half* U = z ? U2y : U2x;
    __half* Pout = z ? P1 : P0;

    int c   = blockIdx.y;
    int mb  = blockIdx.x * 128;
    int tid = threadIdx.x;
    int wid = tid >> 5, lane = tid & 31;
    int wm = wid & 3, wn = wid >> 2;          // 4 m-slabs x 2 n-slabs

    const char* Ab = (const char*)(U + ((size_t)(c * LL + mb)) * KE);
    const char* Bb = (const char*)g_weff2;

    // load A (128x24 chunks) + B (96x24 chunks), swizzle ch^(row&7)
    #pragma unroll
    for (int it = 0; it < 12; it++) {
        int idx = it * 256 + tid;            // 0..3071
        int row = idx / 24, ch = idx - row * 24;
        int chs = ch ^ (row & 7);
        cpa16(sA + row * 384 + chs * 16, Ab + row * 384 + ch * 16);
    }
    #pragma unroll
    for (int it = 0; it < 9; it++) {
        int idx = it * 256 + tid;            // 0..2303
        int row = idx / 24, ch = idx - row * 24;
        int chs = ch ^ (row & 7);
        cpa16(sB + row * 384 + chs * 16, Bb + row * 384 + ch * 16);
    }
    asm volatile("cp.async.commit_group;" ::: "memory");
    asm volatile("cp.async.wait_group 0;" ::: "memory");
    __syncthreads();

    float acc[2][6][4];
    #pragma unroll
    for (int i = 0; i < 2; i++)
        #pragma unroll
        for (int j = 0; j < 6; j++)
            #pragma unroll
            for (int q = 0; q < 4; q++) acc[i][j][q] = 0.f;

    int tr = lane & 15, tc = lane >> 4;

    #pragma unroll
    for (int k = 0; k < 12; k++) {
        uint32_t afr[2][4];
        #pragma unroll
        for (int i = 0; i < 2; i++) {
            int row = wm * 32 + i * 16 + tr;
            uint32_t chs = (uint32_t)(((2 * k + tc) ^ (row & 7)) << 4);
            ldmx4(afr[i][0], afr[i][1], afr[i][2], afr[i][3],
                  sA + row * 384 + chs);
        }
        uint32_t b0[6], b1[6];
        #pragma unroll
        for (int jj = 0; jj < 3; jj++) {
            int row = wn * 48 + jj * 16 + tr;
            uint32_t chs = (uint32_t)(((2 * k + tc) ^ (row & 7)) << 4);
            uint32_t r0, r1, r2, r3;
            ldmx4(r0, r1, r2, r3, sB + row * 384 + chs);
            b0[jj*2]   = r0; b1[jj*2]   = r2;
            b0[jj*2+1] = r1; b1[jj*2+1] = r3;
        }
        #pragma unroll
        for (int i = 0; i < 2; i++)
            #pragma unroll
            for (int j = 0; j < 6; j++)
                mma16816(acc[i][j], afr[i], b0[j], b1[j]);
    }
    __syncthreads();

    // epilogue: leaky + split + stage (uint32, stride 104) + coalesced out
    uint32_t* st = (uint32_t*)smb;
    const float esc = 1.0f / 1048576.0f * VSCALE;   // 2^-20 * 1024 = 2^-10
    int r0 = lane >> 2, c0 = (lane & 3) * 2;
    #pragma unroll
    for (int i = 0; i < 2; i++) {
        #pragma unroll
        for (int j = 0; j < 6; j++) {
            int row = wm * 32 + i * 16 + r0;
            int col = wn * 48 + j * 8 + c0;
            #pragma unroll
            for (int q = 0; q < 4; q++) {
                float v = acc[i][j][q];
                v = (v > 0.f) ? v : 0.2f * v;
                int rr = row + (q >> 1) * 8;
                int cc = col + (q & 1);
                st[rr * 104 + cc] = pack_hilo(v * esc);
            }
        }
    }
    __syncthreads();

    uint4* g4 = (uint4*)((uint32_t*)Pout + ((size_t)(c * LL + mb)) * 96);
    #pragma unroll
    for (int it = 0; it < 12; it++) {
        int idx = it * 256 + tid;            // 0..3071
        int row = idx / 24, q = idx - row * 24;
        g4[row * 24 + q] = *(const uint4*)(st + row * 104 + q * 4);
    }
}

// ---------------- Kernel 3: att GEMM, monolithic single-barrier ------------
#define AT_STAGE 32768
#define AT_SMEM  (3 * AT_STAGE)      // 98304 B

__device__ __forceinline__ void att_load_chunk(uint32_t sAb, uint32_t sBb,
                                               const char* Ab, const char* Bb,
                                               int ck, int tid) {
    #pragma unroll
    for (int it = 0; it < 4; it++) {
        int idx = it * 256 + tid;          // 0..1023
        int row = idx >> 3, ch = idx & 7;
        int chs = ch ^ (row & 7);
        cpa16(sAb + row * 128 + chs * 16, Ab + row * 384 + ck * 128 + ch * 16);
        cpa16(sBb + row * 128 + chs * 16, Bb + row * 384 + ck * 128 + ch * 16);
    }
    asm volatile("cp.async.commit_group;" ::: "memory");
}

__global__ __launch_bounds__(256, 2)
void att_mma(const __half* __restrict__ pA,
             const __half* __restrict__ pB,
             float* __restrict__ att) {
    extern __shared__ char smb[];
    uint32_t sbase = smem_u32(smb);

    int tid  = threadIdx.x;
    int wid  = tid >> 5;
    int lane = tid & 31;
    int wm   = wid & 1;        // 2 m-slabs (64 rows)
    int wn   = wid >> 1;       // 4 n-slabs (32 cols)

    int c  = blockIdx.z;
    int mb = blockIdx.y * 128;
    int nb = blockIdx.x * 128;
    const char* Ab = (const char*)(pA + ((size_t)(c * LL + mb)) * KE);
    const char* Bb = (const char*)(pB + ((size_t)(c * LL + nb)) * KE);

    att_load_chunk(sbase,              sbase + 16384,              Ab, Bb, 0, tid);
    att_load_chunk(sbase + AT_STAGE,   sbase + AT_STAGE + 16384,   Ab, Bb, 1, tid);
    att_load_chunk(sbase + 2*AT_STAGE, sbase + 2*AT_STAGE + 16384, Ab, Bb, 2, tid);

    float acc[4][4][4];
    #pragma unroll
    for (int i = 0; i < 4; i++)
        #pragma unroll
        for (int j = 0; j < 4; j++)
            #pragma unroll
            for (int q = 0; q < 4; q++) acc[i][j][q] = 0.f;

    int tr   = lane & 15;
    int tc   = lane >> 4;
    int xorv = tr & 7;

    asm volatile("cp.async.wait_group 0;" ::: "memory");
    __syncthreads();

    #pragma unroll
    for (int ck = 0; ck < 3; ck++) {
        uint32_t sAb = sbase + ck * AT_STAGE;
        uint32_t sBb = sAb + 16384;
        uint32_t aRow = sAb + (wm * 64 + tr) * 128;
        uint32_t bRow = sBb + (wn * 32 + tr) * 128;

        #pragma unroll
        for (int kk2 = 0; kk2 < 4; kk2++) {
            uint32_t chs = (uint32_t)(((kk2 * 2 + tc) ^ xorv) << 4);
            uint32_t afr[4][4];
            #pragma unroll
            for (int i = 0; i < 4; i++)
                ldmx4(afr[i][0], afr[i][1], afr[i][2], afr[i][3],
                      aRow + i * 2048 + chs);
            uint32_t b0[4], b1[4];
            #pragma unroll
            for (int j = 0; j < 2; j++) {
                uint32_t r0, r1, r2, r3;
                ldmx4(r0, r1, r2, r3, bRow + j * 2048 + chs);
                b0[j*2]   = r0; b1[j*2]   = r2;
                b0[j*2+1] = r1; b1[j*2+1] = r3;
            }
            #pragma unroll
            for (int i = 0; i < 4; i++)
                #pragma unroll
                for (int j = 0; j < 4; j++)
                    mma16816(acc[i][j], afr[i], b0[j], b1[j]);
        }
    }

    // epilogue: product carries VSCALE^2 = 2^20
    const float scale = 1.0f / (81.0f * 1048576.0f);
    int r0 = lane >> 2;
    int c0 = (lane & 3) * 2;
    #pragma unroll
    for (int i = 0; i < 4; i++) {
        #pragma unroll
        for (int j = 0; j < 4; j++) {
            size_t row = (size_t)(mb + wm * 64 + i * 16 + r0);
            float* o = att + (size_t)c * LL * LL + row * LL
                     + nb + wn * 32 + j * 8 + c0;
            *(float2*)o            = make_float2(acc[i][j][0] * scale,
                                                 acc[i][j][1] * scale);
            *(float2*)(o + 8 * LL) = make_float2(acc[i][j][2] * scale,
                                                 acc[i][j][3] * scale);
        }
    }
}

// ---------------- launch ----------------
extern "C" void kernel_launch(void* const* d_in, const int* in_sizes, int n_in,
                              void* d_out, int out_size) {
    const float* x     = (const float*)d_in[0];
    const float* y     = (const float*)d_in[1];
    const float* W_img = (const float*)d_in[2];
    const float* b_img = (const float*)d_in[3];
    const float* W_fea = (const float*)d_in[4];
    const float* b_fea = (const float*)d_in[5];
    const float* W1    = (const float*)d_in[6];
    const float* W2    = (const float*)d_in[7];
    float* out = (float*)d_out;

    uint32_t* we2;
    __half *u2x, *u2y, *pA, *pB;
    cudaGetSymbolAddress((void**)&we2, g_weff2);
    cudaGetSymbolAddress((void**)&u2x, g_u2x);
    cudaGetSymbolAddress((void**)&u2y, g_u2y);
    cudaGetSymbolAddress((void**)&pA,  g_pA);
    cudaGetSymbolAddress((void**)&pB,  g_pB);

    static bool attr_set = false;
    if (!attr_set) {
        cudaFuncSetAttribute(att_mma, cudaFuncAttributeMaxDynamicSharedMemorySize,
                             AT_SMEM);
        cudaFuncSetAttribute(res_trans_tc,
                             cudaFuncAttributeMaxDynamicSharedMemorySize, RT2_SMEM);
        cudaFuncSetAttribute(conv_unfold,
                             cudaFuncAttributeMaxDynamicSharedMemorySize, CV_SMEM);
        attr_set = true;
    }

    weff_kernel<<<96, 96>>>(W1, W2, we2);
    {
        dim3 g(DD, 8, 2);
        conv_unfold<<<g, CV_THREADS, CV_SMEM>>>(x, y, W_img, b_img,
                                                W_fea, b_fea, u2x, u2y);
    }
    {
        dim3 g(LL / 128, CH, 2);          // (8, 32, 2)
        res_trans_tc<<<g, 256, RT2_SMEM>>>(u2x, u2y, pA, pB);
    }
    {
        dim3 g(LL / 128, LL / 128, CH);   // (8, 8, 32)
        att_mma<<<g, 256, AT_SMEM>>>(pA, pB, out);
    }
}

// round 12
// speedup vs baseline: 1.3872x; 1.3872x over previous
#include <cuda_runtime.h>
#include <cuda_fp16.h>
#include <cstdint>

// Shapes (fixed by the problem)
#define CH    32
#define DD    36
#define HH    48
#define WW    48
#define HW    (HH*WW)          // 2304
#define DHW   (DD*HW)          // 82944
#define PP    9
#define P2    81
#define ND    (DD/PP)          // 4
#define NW    (HW/PP)          // 256
#define LL    (ND*NW)          // 1024
#define M2    162              // 2*P2
#define KE2   128              // padded K: [values(81) | 47 zeros], fp16

// ---------------- device scratch (no allocs allowed) ----------------
__device__ float g_wefft[P2 * P2];            // Wefft[j][k] = (W2@W1)[k][j]
__device__ float g_ux[CH * P2 * LL];          // Ut[c][j][l] (K-major, fp32)
__device__ float g_uy[CH * P2 * LL];
__device__ __half g_pA[CH * LL * KE2];        // px rows fp16 [81 | 0-pad]
__device__ __half g_pB[CH * LL * KE2];

// ---------------- f32x2 packed math helpers ----------------
__device__ __forceinline__ unsigned long long ffma2(unsigned long long a,
                                                    unsigned long long b,
                                                    unsigned long long c) {
    unsigned long long d;
    asm("fma.rn.f32x2 %0, %1, %2, %3;" : "=l"(d) : "l"(a), "l"(b), "l"(c));
    return d;
}
__device__ __forceinline__ unsigned long long dup2(float a) {
    unsigned long long d;
    asm("mov.b64 %0, {%1, %1};" : "=l"(d) : "f"(a));
    return d;
}
__device__ __forceinline__ float2 unpack2(unsigned long long v) {
    float2 r;
    asm("mov.b64 {%0, %1}, %2;" : "=f"(r.x), "=f"(r.y) : "l"(v));
    return r;
}

// ---------------- async / mma helpers (plain-target safe) ----------------
__device__ __forceinline__ uint32_t smem_u32(const void* p) {
    uint32_t a;
    asm("{ .reg .u64 t; cvta.to.shared.u64 t, %1; cvt.u32.u64 %0, t; }"
        : "=r"(a) : "l"(p));
    return a;
}
__device__ __forceinline__ void cpa16(uint32_t s, const void* g) {
    asm volatile("cp.async.cg.shared.global [%0], [%1], 16;" :: "r"(s), "l"(g));
}
__device__ __forceinline__ void ldmx4(uint32_t& r0, uint32_t& r1,
                                      uint32_t& r2, uint32_t& r3, uint32_t a) {
    asm volatile("ldmatrix.sync.aligned.m8n8.x4.shared.b16 {%0,%1,%2,%3}, [%4];"
                 : "=r"(r0), "=r"(r1), "=r"(r2), "=r"(r3) : "r"(a));
}
__device__ __forceinline__ void mma16816(float* d, const uint32_t* a,
                                         uint32_t b0, uint32_t b1) {
    asm volatile(
        "mma.sync.aligned.m16n8k16.row.col.f32.f16.f16.f32 "
        "{%0,%1,%2,%3}, {%4,%5,%6,%7}, {%8,%9}, {%0,%1,%2,%3};"
        : "+f"(d[0]), "+f"(d[1]), "+f"(d[2]), "+f"(d[3])
        : "r"(a[0]), "r"(a[1]), "r"(a[2]), "r"(a[3]), "r"(b0), "r"(b1));
}

// ---------------- Kernel 0: Wefft[j][k] = (W2 @ W1)[k][j] ----------------
__global__ void weff_kernel(const float* __restrict__ W1,
                            const float* __restrict__ W2,
                            float* __restrict__ WeT) {
    __shared__ float w2row[M2];
    int k = blockIdx.x;
    int j = threadIdx.x;
    for (int m = j; m < M2; m += P2) w2row[m] = W2[k * M2 + m];
    __syncthreads();
    float s = 0.f;
    #pragma unroll 6
    for (int m = 0; m < M2; m++) s += w2row[m] * W1[m * P2 + j];
    WeT[j * P2 + k] = s;
}

// ---------------- Kernel 1: conv + unfold via smem transpose --------------
// Block: one d-slice (fixed pd,kd), 32 pw values -> 288 voxels, all 32 out ch.
#define CV_THREADS 288
#define CV_SMEM ((9216 + 9216 + 1024 + 32) * 4)    // 73984 B
__global__ __launch_bounds__(CV_THREADS)
void conv_unfold(const float* __restrict__ x, const float* __restrict__ y,
                 const float* __restrict__ Wi, const float* __restrict__ bi,
                 const float* __restrict__ Wf, const float* __restrict__ bf_,
                 float* __restrict__ ux, float* __restrict__ uy) {
    extern __shared__ float cs[];
    float* xs = cs;            // [32][288]
    float* us = cs + 9216;     // [32][288]
    float* ws = cs + 18432;    // [32][32]
    float* bs = cs + 19456;    // [32]

    int z = blockIdx.z;
    const float* src = z ? y : x;
    const float* Wc  = z ? Wf : Wi;
    const float* bc  = z ? bf_ : bi;
    float* U         = z ? uy : ux;

    int tid = threadIdx.x;
    int d   = blockIdx.x;              // 0..35
    int pwb = blockIdx.y;              // 0..7
    int pd = d / PP, kd = d - pd * PP;

    for (int i = tid; i < CH * CH; i += CV_THREADS) ws[i] = Wc[i];
    if (tid < CH) bs[tid] = bc[tid];

    {   // coalesced load: 32 ch x 288 floats (72 float4 per ch)
        const float4* x4 = (const float4*)src;
        float4* xs4 = (float4*)xs;
        int base = d * (HW / 4) + pwb * 72;
        #pragma unroll
        for (int it = 0; it < 8; it++) {
            int idx = it * CV_THREADS + tid;
            int i = idx / 72, q = idx - i * 72;
            xs4[idx] = x4[i * (DHW / 4) + base + q];
        }
    }
    __syncthreads();

    {   // conv: each thread owns one voxel
        int v = tid;
        float xv[CH];
        #pragma unroll
        for (int i = 0; i < CH; i++) xv[i] = xs[i * 288 + v];
        #pragma unroll 4
        for (int c = 0; c < CH; c++) {
            float s = bs[c];
            #pragma unroll
            for (int i = 0; i < CH; i++) s += ws[c * CH + i] * xv[i];
            us[c * 288 + v] = s;
        }
    }
    __syncthreads();

    {   // coalesced write-out: rows (c,kw) of 32 l-values (8 float4)
        int l0 = pd * NW + pwb * 32;
        #pragma unroll
        for (int it = 0; it < 8; it++) {
            int idx = it * CV_THREADS + tid;       // 0..2303
            int row = idx >> 3, q = idx & 7;       // row: c*9+kw
            int c = row / PP, kw = row - c * PP;
            int vb = q * 4 * PP + kw;
            float4 f = make_float4(us[c * 288 + vb],
                                   us[c * 288 + vb + 9],
                                   us[c * 288 + vb + 18],
                                   us[c * 288 + vb + 27]);
            float4* g4 = (float4*)(U + ((size_t)(c * P2 + kd * PP + kw)) * LL + l0);
            g4[q] = f;
        }
    }
}

// ---------------- Kernel 2: folded res_trans + LeakyReLU -> fp16 ----------
// out row (c,l): fp16[128] = [values(81) | 0-pad]
#define RT_BM 64
#define RT_SMEM ((P2 * RT_BM + P2 * 96) * 4)     // 51840 B
__global__ __launch_bounds__(256)
void res_trans_kernel(const float* __restrict__ U0, const float* __restrict__ U1,
                      __half* __restrict__ P0, __half* __restrict__ P1) {
    extern __shared__ float sm[];
    float* As = sm;                   // [81][64]
    float* Bs = sm + P2 * RT_BM;      // [81][96] (cols >= 81 zero)

    int z  = blockIdx.z;
    const float* U = z ? U1 : U0;
    __half* Pout = z ? P1 : P0;

    int c  = blockIdx.y;
    int mb = blockIdx.x * RT_BM;
    int tid = threadIdx.x;
    const float* A = U + c * (P2 * LL);

    for (int idx = tid; idx < P2 * RT_BM; idx += 256) {
        int jj = idx >> 6, m = idx & 63;
        As[idx] = A[jj * LL + mb + m];
    }
    for (int idx = tid; idx < P2 * 96; idx += 256) {
        int jj = idx / 96, n = idx - jj * 96;
        Bs[idx] = (n < P2) ? g_wefft[jj * P2 + n] : 0.f;
    }
    __syncthreads();

    int tx = tid & 15, ty = tid >> 4;
    int m0 = ty * 4, n0 = tx * 6;

    unsigned long long acc[4][3];
    #pragma unroll
    for (int i = 0; i < 4; i++)
        #pragma unroll
        for (int jj = 0; jj < 3; jj++) acc[i][jj] = 0ull;

    #pragma unroll 3
    for (int j = 0; j < P2; j++) {
        float4 a0 = *(const float4*)(As + j * RT_BM + m0);
        const unsigned long long* bp =
            (const unsigned long long*)(Bs + j * 96 + n0);
        unsigned long long b0 = bp[0], b1 = bp[1], b2 = bp[2];
        unsigned long long ad[4];
        ad[0] = dup2(a0.x); ad[1] = dup2(a0.y); ad[2] = dup2(a0.z); ad[3] = dup2(a0.w);
        #pragma unroll
        for (int i = 0; i < 4; i++) {
            acc[i][0] = ffma2(ad[i], b0, acc[i][0]);
            acc[i][1] = ffma2(ad[i], b1, acc[i][1]);
            acc[i][2] = ffma2(ad[i], b2, acc[i][2]);
        }
    }

    __syncthreads();                  // done reading As/Bs
    __half* st = (__half*)sm;         // staging [64][128] fp16 = 16 KB

    // zero pad cols 81..127
    for (int idx = tid; idx < RT_BM * (KE2 - P2); idx += 256) {
        int r = idx / (KE2 - P2), cc = idx - r * (KE2 - P2);
        st[r * KE2 + P2 + cc] = __float2half(0.f);
    }

    #pragma unroll
    for (int i = 0; i < 4; i++) {
        __half* o = st + (m0 + i) * KE2;
        #pragma unroll
        for (int nl = 0; nl < 6; nl++) {
            int n = n0 + nl;
            if (n < P2) {
                float2 u = unpack2(acc[i][nl >> 1]);
                float s = (nl & 1) ? u.y : u.x;
                s = (s > 0.f) ? s : 0.2f * s;
                o[n] = __float2half_rn(s);
            }
        }
    }
    __syncthreads();

    // coalesced copy-out: 64 rows x 256 B = 1024 uint4
    const uint4* s4 = (const uint4*)st;
    uint4* g4 = (uint4*)(Pout + ((size_t)(c * LL + mb)) * KE2);
    #pragma unroll
    for (int i = 0; i < 4; i++) g4[i * 256 + tid] = s4[i * 256 + tid];
}

// ---------------- Kernel 3: att GEMM, fp16 K=128, monolithic ---------------
// CTA tile 128x128; whole K resident: A 32KB + B 32KB = 64 KB, one barrier.
#define AT_SMEM 65536

__global__ __launch_bounds__(256, 2)
void att_mma(const __half* __restrict__ pA,
             const __half* __restrict__ pB,
             float* __restrict__ att) {
    extern __shared__ char smb[];
    uint32_t sA = smem_u32(smb);
    uint32_t sB = sA + 32768;

    int tid  = threadIdx.x;
    int wid  = tid >> 5;
    int lane = tid & 31;
    int wm   = wid & 1;        // 2 m-slabs (64 rows)
    int wn   = wid >> 1;       // 4 n-slabs (32 cols)

    int c  = blockIdx.z;
    int mb = blockIdx.y * 128;
    int nb = blockIdx.x * 128;
    const char* Ab = (const char*)(pA + ((size_t)(c * LL + mb)) * KE2);
    const char* Bb = (const char*)(pB + ((size_t)(c * LL + nb)) * KE2);

    // load both tiles: 128 rows x 256 B each, swizzle ch^(row&7)
    #pragma unroll
    for (int it = 0; it < 8; it++) {
        int idx = it * 256 + tid;          // 0..2047
        int row = idx >> 4, ch = idx & 15;
        int chs = ch ^ (row & 7);
        cpa16(sA + row * 256 + chs * 16, Ab + row * 256 + ch * 16);
        cpa16(sB + row * 256 + chs * 16, Bb + row * 256 + ch * 16);
    }
    asm volatile("cp.async.commit_group;" ::: "memory");

    float acc[4][4][4];
    #pragma unroll
    for (int i = 0; i < 4; i++)
        #pragma unroll
        for (int j = 0; j < 4; j++)
            #pragma unroll
            for (int q = 0; q < 4; q++) acc[i][j][q] = 0.f;

    int tr   = lane & 15;
    int tc   = lane >> 4;
    int xorv = tr & 7;

    asm volatile("cp.async.wait_group 0;" ::: "memory");
    __syncthreads();

    uint32_t aRow = sA + (wm * 64 + tr) * 256;
    uint32_t bRow = sB + (wn * 32 + tr) * 256;

    #pragma unroll
    for (int k = 0; k < 8; k++) {
        uint32_t chs = (uint32_t)(((2 * k + tc) ^ xorv) << 4);
        uint32_t afr[4][4];
        #pragma unroll
        for (int i = 0; i < 4; i++)
            ldmx4(afr[i][0], afr[i][1], afr[i][2], afr[i][3],
                  aRow + i * 4096 + chs);
        uint32_t b0[4], b1[4];
        #pragma unroll
        for (int j = 0; j < 2; j++) {
            uint32_t r0, r1, r2, r3;
            ldmx4(r0, r1, r2, r3, bRow + j * 4096 + chs);
            b0[j*2]   = r0; b1[j*2]   = r2;
            b0[j*2+1] = r1; b1[j*2+1] = r3;
        }
        #pragma unroll
        for (int i = 0; i < 4; i++)
            #pragma unroll
            for (int j = 0; j < 4; j++)
                mma16816(acc[i][j], afr[i], b0[j], b1[j]);
    }

    // epilogue
    const float scale = 1.0f / 81.0f;
    int r0 = lane >> 2;
    int c0 = (lane & 3) * 2;
    #pragma unroll
    for (int i = 0; i < 4; i++) {
        #pragma unroll
        for (int j = 0; j < 4; j++) {
            size_t row = (size_t)(mb + wm * 64 + i * 16 + r0);
            float* o = att + (size_t)c * LL * LL + row * LL
                     + nb + wn * 32 + j * 8 + c0;
            *(float2*)o            = make_float2(acc[i][j][0] * scale,
                                                 acc[i][j][1] * scale);
            *(float2*)(o + 8 * LL) = make_float2(acc[i][j][2] * scale,
                                                 acc[i][j][3] * scale);
        }
    }
}

// ---------------- launch ----------------
extern "C" void kernel_launch(void* const* d_in, const int* in_sizes, int n_in,
                              void* d_out, int out_size) {
    const float* x     = (const float*)d_in[0];
    const float* y     = (const float*)d_in[1];
    const float* W_img = (const float*)d_in[2];
    const float* b_img = (const float*)d_in[3];
    const float* W_fea = (const float*)d_in[4];
    const float* b_fea = (const float*)d_in[5];
    const float* W1    = (const float*)d_in[6];
    const float* W2    = (const float*)d_in[7];
    float* out = (float*)d_out;

    float *weT, *ux, *uy;
    __half *pA, *pB;
    cudaGetSymbolAddress((void**)&weT, g_wefft);
    cudaGetSymbolAddress((void**)&ux,  g_ux);
    cudaGetSymbolAddress((void**)&uy,  g_uy);
    cudaGetSymbolAddress((void**)&pA,  g_pA);
    cudaGetSymbolAddress((void**)&pB,  g_pB);

    static bool attr_set = false;
    if (!attr_set) {
        cudaFuncSetAttribute(att_mma, cudaFuncAttributeMaxDynamicSharedMemorySize,
                             AT_SMEM);
        cudaFuncSetAttribute(res_trans_kernel,
                             cudaFuncAttributeMaxDynamicSharedMemorySize, RT_SMEM);
        cudaFuncSetAttribute(conv_unfold,
                             cudaFuncAttributeMaxDynamicSharedMemorySize, CV_SMEM);
        attr_set = true;
    }

    weff_kernel<<<P2, P2>>>(W1, W2, weT);
    {
        dim3 g(DD, 8, 2);
        conv_unfold<<<g, CV_THREADS, CV_SMEM>>>(x, y, W_img, b_img,
                                                W_fea, b_fea, ux, uy);
    }
    {
        dim3 g(LL / RT_BM, CH, 2);
        res_trans_kernel<<<g, 256, RT_SMEM>>>(ux, uy, pA, pB);
    }
    {
        dim3 g(LL / 128, LL / 128, CH);   // (8, 8, 32)
        att_mma<<<g, 256, AT_SMEM>>>(pA, pB, out);
    }
}

// round 13
// speedup vs baseline: 1.8239x; 1.3148x over previous
#include <cuda_runtime.h>
#include <cuda_fp16.h>
#include <cstdint>

// Shapes (fixed by the problem)
#define CH    32
#define DD    36
#define HH    48
#define WW    48
#define HW    (HH*WW)          // 2304
#define DHW   (DD*HW)          // 82944
#define PP    9
#define P2    81
#define ND    (DD/PP)          // 4
#define NW    (HW/PP)          // 256
#define LL    (ND*NW)          // 1024
#define M2    162              // 2*P2
#define KE2   128              // padded K: [values(81) | 47 zeros], fp16

// ---------------- device scratch (no allocs allowed) ----------------
__device__ __align__(16) __half g_weff2h[96 * 104];   // Wefft fp16 [kout][j], pads 0
__device__ float g_ux[CH * P2 * LL];          // Ut[c][j][l] (K-major, fp32)
__device__ float g_uy[CH * P2 * LL];
__device__ __half g_pA[CH * LL * KE2];        // px rows fp16 [81 | 0-pad]
__device__ __half g_pB[CH * LL * KE2];

// ---------------- helpers ----------------
__device__ __forceinline__ uint32_t smem_u32(const void* p) {
    uint32_t a;
    asm("{ .reg .u64 t; cvta.to.shared.u64 t, %1; cvt.u32.u64 %0, t; }"
        : "=r"(a) : "l"(p));
    return a;
}
__device__ __forceinline__ void cpa16(uint32_t s, const void* g) {
    asm volatile("cp.async.cg.shared.global [%0], [%1], 16;" :: "r"(s), "l"(g));
}
__device__ __forceinline__ void ldmx4(uint32_t& r0, uint32_t& r1,
                                      uint32_t& r2, uint32_t& r3, uint32_t a) {
    asm volatile("ldmatrix.sync.aligned.m8n8.x4.shared.b16 {%0,%1,%2,%3}, [%4];"
                 : "=r"(r0), "=r"(r1), "=r"(r2), "=r"(r3) : "r"(a));
}
__device__ __forceinline__ void ldmx4t(uint32_t& r0, uint32_t& r1,
                                       uint32_t& r2, uint32_t& r3, uint32_t a) {
    asm volatile("ldmatrix.sync.aligned.m8n8.x4.trans.shared.b16 {%0,%1,%2,%3}, [%4];"
                 : "=r"(r0), "=r"(r1), "=r"(r2), "=r"(r3) : "r"(a));
}
__device__ __forceinline__ void mma16816(float* d, const uint32_t* a,
                                         uint32_t b0, uint32_t b1) {
    asm volatile(
        "mma.sync.aligned.m16n8k16.row.col.f32.f16.f16.f32 "
        "{%0,%1,%2,%3}, {%4,%5,%6,%7}, {%8,%9}, {%0,%1,%2,%3};"
        : "+f"(d[0]), "+f"(d[1]), "+f"(d[2]), "+f"(d[3])
        : "r"(a[0]), "r"(a[1]), "r"(a[2]), "r"(a[3]), "r"(b0), "r"(b1));
}

// ---------------- Kernel 0: Weff fp16  [kout 96][j 104], pads zero ----------
__global__ void weff_kernel(const float* __restrict__ W1,
                            const float* __restrict__ W2,
                            __half* __restrict__ We2) {
    __shared__ float w2row[M2];
    int k = blockIdx.x;     // 0..95
    int j = threadIdx.x;    // 0..103
    if (k < P2)
        for (int m = j; m < M2; m += 104) w2row[m] = W2[k * M2 + m];
    __syncthreads();
    float s = 0.f;
    if (k < P2 && j < P2) {
        #pragma unroll 6
        for (int m = 0; m < M2; m++) s += w2row[m] * W1[m * P2 + j];
    }
    We2[k * 104 + j] = __float2half_rn(s);
}

// ---------------- Kernel 1: conv + unfold via smem transpose --------------
#define CV_THREADS 288
#define CV_SMEM ((9216 + 9216 + 1024 + 32) * 4)    // 73984 B
__global__ __launch_bounds__(CV_THREADS)
void conv_unfold(const float* __restrict__ x, const float* __restrict__ y,
                 const float* __restrict__ Wi, const float* __restrict__ bi,
                 const float* __restrict__ Wf, const float* __restrict__ bf_,
                 float* __restrict__ ux, float* __restrict__ uy) {
    extern __shared__ float cs[];
    float* xs = cs;            // [32][288]
    float* us = cs + 9216;     // [32][288]
    float* ws = cs + 18432;    // [32][32]
    float* bs = cs + 19456;    // [32]

    int z = blockIdx.z;
    const float* src = z ? y : x;
    const float* Wc  = z ? Wf : Wi;
    const float* bc  = z ? bf_ : bi;
    float* U         = z ? uy : ux;

    int tid = threadIdx.x;
    int d   = blockIdx.x;              // 0..35
    int pwb = blockIdx.y;              // 0..7
    int pd = d / PP, kd = d - pd * PP;

    for (int i = tid; i < CH * CH; i += CV_THREADS) ws[i] = Wc[i];
    if (tid < CH) bs[tid] = bc[tid];

    {   // coalesced load: 32 ch x 288 floats
        const float4* x4 = (const float4*)src;
        float4* xs4 = (float4*)xs;
        int base = d * (HW / 4) + pwb * 72;
        #pragma unroll
        for (int it = 0; it < 8; it++) {
            int idx = it * CV_THREADS + tid;
            int i = idx / 72, q = idx - i * 72;
            xs4[idx] = x4[i * (DHW / 4) + base + q];
        }
    }
    __syncthreads();

    {   // conv: each thread owns one voxel
        int v = tid;
        float xv[CH];
        #pragma unroll
        for (int i = 0; i < CH; i++) xv[i] = xs[i * 288 + v];
        #pragma unroll 4
        for (int c = 0; c < CH; c++) {
            float s = bs[c];
            #pragma unroll
            for (int i = 0; i < CH; i++) s += ws[c * CH + i] * xv[i];
            us[c * 288 + v] = s;
        }
    }
    __syncthreads();

    {   // coalesced write-out: rows (c,kw) of 32 l-values (8 float4)
        int l0 = pd * NW + pwb * 32;
        #pragma unroll
        for (int it = 0; it < 8; it++) {
            int idx = it * CV_THREADS + tid;       // 0..2303
            int row = idx >> 3, q = idx & 7;       // row: c*9+kw
            int c = row / PP, kw = row - c * PP;
            int vb = q * 4 * PP + kw;
            float4 f = make_float4(us[c * 288 + vb],
                                   us[c * 288 + vb + 9],
                                   us[c * 288 + vb + 18],
                                   us[c * 288 + vb + 27]);
            float4* g4 = (float4*)(U + ((size_t)(c * P2 + kd * PP + kw)) * LL + l0);
            g4[q] = f;
        }
    }
}

// ---------------- Kernel 2: res_trans on tensor cores ----------------------
// A = Weff fp16 [m=kout 96][k=j 96], B = sU[k=j][n=l 128] via ldmatrix.trans.
// D[m][n] -> leaky -> st[l][kout] -> coalesced fp16 rows [l][128] (pad zero).
#define SU_STRIDE 272                         // bytes per sU row (17*16)
#define SW_STRIDE 208                         // bytes per sW row (13*16)
#define RT2_SMEM (96 * SU_STRIDE + 96 * SW_STRIDE)   // 26112+19968 = 46080 B
__global__ __launch_bounds__(256)
void res_trans_tc(const float* __restrict__ U0, const float* __restrict__ U1,
                  __half* __restrict__ P0, __half* __restrict__ P1) {
    extern __shared__ char smb[];
    uint32_t sU = smem_u32(smb);
    uint32_t sW = sU + 96 * SU_STRIDE;

    int z  = blockIdx.z;
    const float* U = z ? U1 : U0;
    __half* Pout = z ? P1 : P0;

    int c   = blockIdx.y;
    int mb  = blockIdx.x * 128;
    int tid = threadIdx.x;
    int wid = tid >> 5, lane = tid & 31;
    int wm = wid & 1, wn = wid >> 1;          // m-slab 48 (x2), n-slab 32 (x4)

    // build sU[j][l] fp16: coalesced float4 reads along l, half4 stores
    const float* Ub = U + (size_t)c * (P2 * LL) + mb;
    #pragma unroll
    for (int it = 0; it < 12; it++) {
        int idx = it * 256 + tid;            // 0..3071 = 96 rows x 32 chunks
        int j = idx >> 5, lc = idx & 31;
        uint2 v;
        if (j < P2) {
            float4 f = *(const float4*)(Ub + (size_t)j * LL + lc * 4);
            __half2 h0 = __floats2half2_rn(f.x, f.y);
            __half2 h1 = __floats2half2_rn(f.z, f.w);
            v.x = *(uint32_t*)&h0; v.y = *(uint32_t*)&h1;
        } else { v.x = 0u; v.y = 0u; }
        *(uint2*)(smb + (sU - smem_u32(smb)) + j * SU_STRIDE + lc * 8) = v;
    }
    // load sW (Weff fp16, 96x13 16B chunks) via cp.async
    {
        const char* gW = (const char*)g_weff2h;
        for (int idx = tid; idx < 96 * 13; idx += 256) {
            int row = idx / 13, ch = idx - row * 13;
            cpa16(sW + row * SW_STRIDE + ch * 16, gW + row * SW_STRIDE + ch * 16);
        }
        asm volatile("cp.async.commit_group;" ::: "memory");
        asm volatile("cp.async.wait_group 0;" ::: "memory");
    }
    __syncthreads();

    float acc[3][4][4];
    #pragma unroll
    for (int i = 0; i < 3; i++)
        #pragma unroll
        for (int j = 0; j < 4; j++)
            #pragma unroll
            for (int q = 0; q < 4; q++) acc[i][j][q] = 0.f;

    int tr = lane & 15, tc = lane >> 4;

    #pragma unroll
    for (int ks = 0; ks < 6; ks++) {
        int j0 = ks * 16;
        uint32_t afr[3][4];
        #pragma unroll
        for (int i = 0; i < 3; i++) {
            int m0 = wm * 48 + i * 16;
            ldmx4(afr[i][0], afr[i][1], afr[i][2], afr[i][3],
                  sW + (m0 + tr) * SW_STRIDE + j0 * 2 + tc * 16);
        }
        uint32_t b0[4], b1[4];
        #pragma unroll
        for (int jj = 0; jj < 2; jj++) {
            int n0 = wn * 32 + jj * 16;
            uint32_t r0, r1, r2, r3;
            ldmx4t(r0, r1, r2, r3,
                   sU + (j0 + tr) * SU_STRIDE + (n0 + tc * 8) * 2);
            b0[jj*2]   = r0; b1[jj*2]   = r1;   // n-tile n0
            b0[jj*2+1] = r2; b1[jj*2+1] = r3;   // n-tile n0+8
        }
        #pragma unroll
        for (int i = 0; i < 3; i++)
            #pragma unroll
            for (int j = 0; j < 4; j++)
                mma16816(acc[i][j], afr[i], b0[j], b1[j]);
    }
    __syncthreads();

    // stage transposed: st[l][kout], stride 104 halves (208 B)
    __half* st = (__half*)smb;
    int r0 = lane >> 2, c0 = (lane & 3) * 2;
    #pragma unroll
    for (int i = 0; i < 3; i++) {
        #pragma unroll
        for (int j = 0; j < 4; j++) {
            int m0 = wm * 48 + i * 16 + r0;
            int n0 = wn * 32 + j * 8 + c0;
            #pragma unroll
            for (int q = 0; q < 4; q++) {
                float v = acc[i][j][q];
                v = (v > 0.f) ? v : 0.2f * v;
                int mm = m0 + (q >> 1) * 8;
                int nn = n0 + (q & 1);
                st[nn * 104 + mm] = __float2half_rn(v);
            }
        }
    }
    __syncthreads();

    // coalesced out: 128 rows x (12 data + 4 zero) uint4
    uint4* g4 = (uint4*)(Pout + ((size_t)(c * LL + mb)) * KE2);
    const char* stb = smb;
    uint4 zero4 = make_uint4(0, 0, 0, 0);
    #pragma unroll
    for (int it = 0; it < 8; it++) {
        int idx = it * 256 + tid;            // 0..2047
        int r = idx >> 4, q = idx & 15;
        uint4 v = (q < 12) ? *(const uint4*)(stb + r * SW_STRIDE + q * 16) : zero4;
        g4[r * 16 + q] = v;
    }
}

// ---------------- Kernel 3: att GEMM, fp16 K=128, monolithic ---------------
#define AT_SMEM 65536
__global__ __launch_bounds__(256, 2)
void att_mma(const __half* __restrict__ pA,
             const __half* __restrict__ pB,
             float* __restrict__ att) {
    extern __shared__ char smb[];
    uint32_t sA = smem_u32(smb);
    uint32_t sB = sA + 32768;

    int tid  = threadIdx.x;
    int wid  = tid >> 5;
    int lane = tid & 31;
    int wm   = wid & 1;
    int wn   = wid >> 1;

    int c  = blockIdx.z;
    int mb = blockIdx.y * 128;
    int nb = blockIdx.x * 128;
    const char* Ab = (const char*)(pA + ((size_t)(c * LL + mb)) * KE2);
    const char* Bb = (const char*)(pB + ((size_t)(c * LL + nb)) * KE2);

    #pragma unroll
    for (int it = 0; it < 8; it++) {
        int idx = it * 256 + tid;
        int row = idx >> 4, ch = idx & 15;
        int chs = ch ^ (row & 7);
        cpa16(sA + row * 256 + chs * 16, Ab + row * 256 + ch * 16);
        cpa16(sB + row * 256 + chs * 16, Bb + row * 256 + ch * 16);
    }
    asm volatile("cp.async.commit_group;" ::: "memory");

    float acc[4][4][4];
    #pragma unroll
    for (int i = 0; i < 4; i++)
        #pragma unroll
        for (int j = 0; j < 4; j++)
            #pragma unroll
            for (int q = 0; q < 4; q++) acc[i][j][q] = 0.f;

    int tr   = lane & 15;
    int tc   = lane >> 4;
    int xorv = tr & 7;

    asm volatile("cp.async.wait_group 0;" ::: "memory");
    __syncthreads();

    uint32_t aRow = sA + (wm * 64 + tr) * 256;
    uint32_t bRow = sB + (wn * 32 + tr) * 256;

    #pragma unroll
    for (int k = 0; k < 8; k++) {
        uint32_t chs = (uint32_t)(((2 * k + tc) ^ xorv) << 4);
        uint32_t afr[4][4];
        #pragma unroll
        for (int i = 0; i < 4; i++)
            ldmx4(afr[i][0], afr[i][1], afr[i][2], afr[i][3],
                  aRow + i * 4096 + chs);
        uint32_t b0[4], b1[4];
        #pragma unroll
        for (int j = 0; j < 2; j++) {
            uint32_t r0, r1, r2, r3;
            ldmx4(r0, r1, r2, r3, bRow + j * 4096 + chs);
            b0[j*2]   = r0; b1[j*2]   = r2;
            b0[j*2+1] = r1; b1[j*2+1] = r3;
        }
        #pragma unroll
        for (int i = 0; i < 4; i++)
            #pragma unroll
            for (int j = 0; j < 4; j++)
                mma16816(acc[i][j], afr[i], b0[j], b1[j]);
    }

    const float scale = 1.0f / 81.0f;
    int r0 = lane >> 2;
    int c0 = (lane & 3) * 2;
    #pragma unroll
    for (int i = 0; i < 4; i++) {
        #pragma unroll
        for (int j = 0; j < 4; j++) {
            size_t row = (size_t)(mb + wm * 64 + i * 16 + r0);
            float* o = att + (size_t)c * LL * LL + row * LL
                     + nb + wn * 32 + j * 8 + c0;
            *(float2*)o            = make_float2(acc[i][j][0] * scale,
                                                 acc[i][j][1] * scale);
            *(float2*)(o + 8 * LL) = make_float2(acc[i][j][2] * scale,
                                                 acc[i][j][3] * scale);
        }
    }
}

// ---------------- launch ----------------
extern "C" void kernel_launch(void* const* d_in, const int* in_sizes, int n_in,
                              void* d_out, int out_size) {
    const float* x     = (const float*)d_in[0];
    const float* y     = (const float*)d_in[1];
    const float* W_img = (const float*)d_in[2];
    const float* b_img = (const float*)d_in[3];
    const float* W_fea = (const float*)d_in[4];
    const float* b_fea = (const float*)d_in[5];
    const float* W1    = (const float*)d_in[6];
    const float* W2    = (const float*)d_in[7];
    float* out = (float*)d_out;

    float *ux, *uy;
    __half *we2, *pA, *pB;
    cudaGetSymbolAddress((void**)&we2, g_weff2h);
    cudaGetSymbolAddress((void**)&ux,  g_ux);
    cudaGetSymbolAddress((void**)&uy,  g_uy);
    cudaGetSymbolAddress((void**)&pA,  g_pA);
    cudaGetSymbolAddress((void**)&pB,  g_pB);

    static bool attr_set = false;
    if (!attr_set) {
        cudaFuncSetAttribute(att_mma, cudaFuncAttributeMaxDynamicSharedMemorySize,
                             AT_SMEM);
        cudaFuncSetAttribute(res_trans_tc,
                             cudaFuncAttributeMaxDynamicSharedMemorySize, RT2_SMEM);
        cudaFuncSetAttribute(conv_unfold,
                             cudaFuncAttributeMaxDynamicSharedMemorySize, CV_SMEM);
        attr_set = true;
    }

    weff_kernel<<<96, 104>>>(W1, W2, we2);
    {
        dim3 g(DD, 8, 2);
        conv_unfold<<<g, CV_THREADS, CV_SMEM>>>(x, y, W_img, b_img,
                                                W_fea, b_fea, ux, uy);
    }
    {
        dim3 g(LL / 128, CH, 2);          // (8, 32, 2)
        res_trans_tc<<<g, 256, RT2_SMEM>>>(ux, uy, pA, pB);
    }
    {
        dim3 g(LL / 128, LL / 128, CH);   // (8, 8, 32)
        att_mma<<<g, 256, AT_SMEM>>>(pA, pB, out);
    }
}